// round 9
// baseline (speedup 1.0000x reference)
#include <cuda_runtime.h>
#include <cstdint>

#define D_IN   1024
#define DMODEL 1024
#define BB     4
#define NN     2048
#define NH     16
#define HD     64
#define MTOT   (BB*NN)   // 8192

// Scratch (device globals: allocation-free rule)
__device__ float g_q[(size_t)BB*NH*NN*HD];
__device__ float g_k[(size_t)BB*NH*NN*HD];
__device__ float g_v[(size_t)BB*NH*NN*HD];
__device__ float g_ctx[(size_t)MTOT*DMODEL];

__device__ __forceinline__ float to_tf32(float x) {
    float r;
    asm("cvt.rna.tf32.f32 %0, %1;" : "=f"(r) : "f"(x));
    return r;
}

// D += A(16x8,row) * B(8x8,col)  fp32 accum, tf32 operands (bits in fp32 regs)
__device__ __forceinline__ void mma_tf32(float c[4], float a0, float a1, float a2, float a3,
                                         float b0, float b1) {
    asm("mma.sync.aligned.m16n8k8.row.col.f32.tf32.tf32.f32 "
        "{%0,%1,%2,%3},{%4,%5,%6,%7},{%8,%9},{%0,%1,%2,%3};"
        : "+f"(c[0]), "+f"(c[1]), "+f"(c[2]), "+f"(c[3])
        : "r"(__float_as_uint(a0)), "r"(__float_as_uint(a1)),
          "r"(__float_as_uint(a2)), "r"(__float_as_uint(a3)),
          "r"(__float_as_uint(b0)), "r"(__float_as_uint(b1)));
}

// ---------------------------------------------------------------------------
// TF32 GEMM. CTA tile 128(m) x 256(n), K-tile 16, 256 thr = 8 warps (2m x 4n),
// warp tile 64x64 = 4x8 frags m16n8k8. A stored k-permuted (+row-XOR) so each
// thread's A-fragment regs for two k-steps are ONE float4 LDS (conflict-free,
// stride exactly 16). B plain [k][n], stride 264 (==8 mod 32 -> conflict-free
// scalar b-loads). Double buffered, one barrier per k-tile.
// mode 0: A=X, W per blockIdx.z, scatter into g_q/g_k/g_v [b,h,n,d]
// mode 1: A=g_ctx, W=W0, out = A@W + bias
// ---------------------------------------------------------------------------
#define GB_STRIDE 264
#define GEMM_SMEM ((2*128*16 + 2*16*GB_STRIDE) * 4)   // 50176 B

__global__ __launch_bounds__(256, 1)
void gemm_tc(const float* __restrict__ Xp,
             const float* __restrict__ W0,
             const float* __restrict__ W1,
             const float* __restrict__ W2,
             const float* __restrict__ bias,
             float* __restrict__ outp,
             int mode)
{
    extern __shared__ float smg[];
    float* As = smg;                    // [2][128][16] permuted
    float* Bs = smg + 2 * 128 * 16;     // [2][16][264]

    const int tid  = threadIdx.x;
    const int lane = tid & 31;
    const int warp = tid >> 5;
    const int wm   = warp >> 2;        // 0..1  (64 rows)
    const int wn   = warp & 3;         // 0..3  (64 cols)
    const int qr   = lane >> 2;        // 0..7
    const int qi   = lane & 3;         // 0..3
    const int bx   = blockIdx.x;
    const int by   = blockIdx.y;
    const int z    = blockIdx.z;

    const float* A = (mode == 0) ? Xp : (const float*)g_ctx;
    const float* W = (mode == 0) ? ((z == 0) ? W0 : (z == 1) ? W1 : W2) : W0;

    const float* Abase = A + (size_t)by * 128 * D_IN;
    const float* Bbase = W + bx * 256;

    float c[4][8][4];
#pragma unroll
    for (int mf = 0; mf < 4; mf++)
#pragma unroll
        for (int nf = 0; nf < 8; nf++)
#pragma unroll
            for (int k = 0; k < 4; k++) c[mf][nf][k] = 0.f;

    // loader indices: A 128x16 = 512 f4 (2/thread); B 16x256 = 1024 f4 (4/thr)
    const int aR0 = tid >> 2,        aG0 = tid & 3;
    const int aR1 = (tid + 256) >> 2, aG1 = aG0;

    float4 pa[2], pb[4];

    // ---- preload tile 0 ----
    pa[0] = *(const float4*)(Abase + (size_t)aR0 * D_IN + aG0 * 4);
    pa[1] = *(const float4*)(Abase + (size_t)aR1 * D_IN + aG1 * 4);
#pragma unroll
    for (int l = 0; l < 4; l++) {
        const int idx = tid + l * 256;
        pb[l] = *(const float4*)(Bbase + (size_t)(idx >> 6) * DMODEL + (idx & 63) * 4);
    }
    // store tile 0 -> buf 0
    {
        // A permuted scatter: k = g*4 + j  ->  kp = (j ^ (row&3))*4 + g
        float* p0 = As + aR0 * 16 + aG0;
        const int x0 = (aR0 & 3) << 2;
        p0[(0 ^ x0)] = to_tf32(pa[0].x); p0[(4 ^ x0)] = to_tf32(pa[0].y);
        p0[(8 ^ x0)] = to_tf32(pa[0].z); p0[(12 ^ x0)] = to_tf32(pa[0].w);
        float* p1 = As + aR1 * 16 + aG1;
        const int x1 = (aR1 & 3) << 2;
        p1[(0 ^ x1)] = to_tf32(pa[1].x); p1[(4 ^ x1)] = to_tf32(pa[1].y);
        p1[(8 ^ x1)] = to_tf32(pa[1].z); p1[(12 ^ x1)] = to_tf32(pa[1].w);
#pragma unroll
        for (int l = 0; l < 4; l++) {
            const int idx = tid + l * 256;
            float4 t;
            t.x = to_tf32(pb[l].x); t.y = to_tf32(pb[l].y);
            t.z = to_tf32(pb[l].z); t.w = to_tf32(pb[l].w);
            *(float4*)&Bs[(idx >> 6) * GB_STRIDE + (idx & 63) * 4] = t;
        }
    }
    __syncthreads();

    const int KT = D_IN / 16;  // 64
    for (int kt = 0; kt < KT; kt++) {
        const int buf = kt & 1;
        float* Ab = As + buf * 128 * 16;
        float* Bb = Bs + buf * 16 * GB_STRIDE;
        if (kt < KT - 1) {
            const int ko = (kt + 1) * 16;
            pa[0] = *(const float4*)(Abase + (size_t)aR0 * D_IN + ko + aG0 * 4);
            pa[1] = *(const float4*)(Abase + (size_t)aR1 * D_IN + ko + aG1 * 4);
#pragma unroll
            for (int l = 0; l < 4; l++) {
                const int idx = tid + l * 256;
                pb[l] = *(const float4*)(Bbase + (size_t)(ko + (idx >> 6)) * DMODEL + (idx & 63) * 4);
            }
        }

        // A fragments: 8 float4 cover all regs for BOTH k-steps
        float4 fal[4], fah[4];
#pragma unroll
        for (int mf = 0; mf < 4; mf++) {
            const int r0 = wm * 64 + mf * 16 + qr;
            const int off = ((qi ^ (r0 & 3)) << 2);
            fal[mf] = *(const float4*)&Ab[r0 * 16 + off];
            fah[mf] = *(const float4*)&Ab[(r0 + 8) * 16 + off];
        }
#pragma unroll
        for (int ks = 0; ks < 2; ks++) {
            float b0[8], b1[8];
#pragma unroll
            for (int nf = 0; nf < 8; nf++) {
                const int cB = wn * 64 + nf * 8 + qr;
                b0[nf] = Bb[(ks * 8 + qi) * GB_STRIDE + cB];
                b1[nf] = Bb[(ks * 8 + qi + 4) * GB_STRIDE + cB];
            }
#pragma unroll
            for (int mf = 0; mf < 4; mf++) {
                const float a0 = ks ? fal[mf].z : fal[mf].x;
                const float a1 = ks ? fah[mf].z : fah[mf].x;
                const float a2 = ks ? fal[mf].w : fal[mf].y;
                const float a3 = ks ? fah[mf].w : fah[mf].y;
#pragma unroll
                for (int nf = 0; nf < 8; nf++)
                    mma_tf32(c[mf][nf], a0, a1, a2, a3, b0[nf], b1[nf]);
            }
        }

        if (kt < KT - 1) {
            const int nb = buf ^ 1;
            float* An = As + nb * 128 * 16;
            float* Bn = Bs + nb * 16 * GB_STRIDE;
            float* p0 = An + aR0 * 16 + aG0;
            const int x0 = (aR0 & 3) << 2;
            p0[(0 ^ x0)] = to_tf32(pa[0].x); p0[(4 ^ x0)] = to_tf32(pa[0].y);
            p0[(8 ^ x0)] = to_tf32(pa[0].z); p0[(12 ^ x0)] = to_tf32(pa[0].w);
            float* p1 = An + aR1 * 16 + aG1;
            const int x1 = (aR1 & 3) << 2;
            p1[(0 ^ x1)] = to_tf32(pa[1].x); p1[(4 ^ x1)] = to_tf32(pa[1].y);
            p1[(8 ^ x1)] = to_tf32(pa[1].z); p1[(12 ^ x1)] = to_tf32(pa[1].w);
#pragma unroll
            for (int l = 0; l < 4; l++) {
                const int idx = tid + l * 256;
                float4 t;
                t.x = to_tf32(pb[l].x); t.y = to_tf32(pb[l].y);
                t.z = to_tf32(pb[l].z); t.w = to_tf32(pb[l].w);
                *(float4*)&Bn[(idx >> 6) * GB_STRIDE + (idx & 63) * 4] = t;
            }
            __syncthreads();
        }
    }

    // ---- epilogue ----
    if (mode == 0) {
        float* O = (z == 0) ? g_q : (z == 1) ? g_k : g_v;
#pragma unroll
        for (int mf = 0; mf < 4; mf++)
#pragma unroll
            for (int nf = 0; nf < 8; nf++)
#pragma unroll
                for (int ci = 0; ci < 4; ci++) {
                    const int m = by * 128 + wm * 64 + mf * 16 + qr + ((ci >= 2) ? 8 : 0);
                    const int col = bx * 256 + wn * 64 + nf * 8 + 2 * qi + (ci & 1);
                    const int b_ = m >> 11, n_ = m & (NN - 1);
                    const int h_ = col >> 6, d_ = col & (HD - 1);
                    O[(((size_t)(b_ * NH + h_)) * NN + n_) * HD + d_] = c[mf][nf][ci];
                }
    } else {
#pragma unroll
        for (int mf = 0; mf < 4; mf++)
#pragma unroll
            for (int nf = 0; nf < 8; nf++)
#pragma unroll
                for (int ci = 0; ci < 4; ci++) {
                    const int m = by * 128 + wm * 64 + mf * 16 + qr + ((ci >= 2) ? 8 : 0);
                    const int col = bx * 256 + wn * 64 + nf * 8 + 2 * qi + (ci & 1);
                    outp[(size_t)m * DMODEL + col] = c[mf][nf][ci] + bias[col];
                }
    }
}

// ---------------------------------------------------------------------------
// Flash attention (causal), tensor cores. 128 thr = 4 warps x 16 q-rows.
// Q and K stored k-permuted (+row-XOR, stride 80) -> float4 fragment LDS.
// V plain [token][d] stride 72 (conflict-free scalar b-loads).
// P stays in REGISTERS: C-frag -> A-frag permutation via quad shuffles
// (no P smem round-trip, no extra barriers). exp2f softmax, log2e in Q scale.
// ---------------------------------------------------------------------------
#define AQ_STRIDE 80
#define AV_STRIDE 72
#define ATTN_SMEM ((2*64*AQ_STRIDE + 64*AV_STRIDE) * 4)   // 59392 B

__global__ __launch_bounds__(128, 3)
void attn_tc()
{
    extern __shared__ float sm[];
    float* Qs = sm;                        // [64][80] permuted
    float* Ks = sm + 64 * AQ_STRIDE;       // [64][80] permuted
    float* Vs = sm + 2 * 64 * AQ_STRIDE;   // [64][72]

    const int tid  = threadIdx.x;
    const int lane = tid & 31;
    const int w    = tid >> 5;
    const int qr   = lane >> 2;
    const int qi   = lane & 3;
    const int qt   = blockIdx.x;
    const int bh   = blockIdx.y;

    const float* Qg = g_q + ((size_t)bh * NN + qt * 64) * HD;
    const float* Kg = g_k + (size_t)bh * NN * HD;
    const float* Vg = g_v + (size_t)bh * NN * HD;

    const float qscale = 0.125f * 1.44269504088896f;  // 1/sqrt(64) * log2(e)

    // ---- Q tile: float4 loads, permuted scatter stores ----
#pragma unroll
    for (int p = 0; p < 8; p++) {
        const int idx = p * 128 + tid;
        const int r = idx >> 4, g = idx & 15;
        float4 v = *(const float4*)(Qg + r * 64 + g * 4);
        float* dst = Qs + r * AQ_STRIDE + (g >> 2) * 16 + (g & 3);
        const int x = (r & 3) << 2;
        dst[(0 ^ x)]  = to_tf32(v.x * qscale);
        dst[(4 ^ x)]  = to_tf32(v.y * qscale);
        dst[(8 ^ x)]  = to_tf32(v.z * qscale);
        dst[(12 ^ x)] = to_tf32(v.w * qscale);
    }

    float m0 = -1e30f, m1 = -1e30f, l0 = 0.f, l1 = 0.f;
    float o[8][4];
#pragma unroll
    for (int nf = 0; nf < 8; nf++)
#pragma unroll
        for (int ci = 0; ci < 4; ci++) o[nf][ci] = 0.f;

    const int ar   = w * 16 + qr;
    const int aoff = ((qi ^ (ar & 3)) << 2);
    const int q2   = (lane & 28) | (qi >> 1);

    for (int kt = 0; kt <= qt; kt++) {
        __syncthreads();   // prior K/V reads done (Q visible at kt=0)
        const float* Ktg = Kg + (size_t)kt * 64 * HD;
        const float* Vtg = Vg + (size_t)kt * 64 * HD;
#pragma unroll
        for (int p = 0; p < 8; p++) {
            const int idx = p * 128 + tid;
            const int r = idx >> 4, g = idx & 15;
            float4 kv = *(const float4*)(Ktg + r * 64 + g * 4);
            float* dk = Ks + r * AQ_STRIDE + (g >> 2) * 16 + (g & 3);
            const int x = (r & 3) << 2;
            dk[(0 ^ x)]  = to_tf32(kv.x);
            dk[(4 ^ x)]  = to_tf32(kv.y);
            dk[(8 ^ x)]  = to_tf32(kv.z);
            dk[(12 ^ x)] = to_tf32(kv.w);
            float4 vv = *(const float4*)(Vtg + r * 64 + g * 4);
            float4 t;
            t.x = to_tf32(vv.x); t.y = to_tf32(vv.y);
            t.z = to_tf32(vv.z); t.w = to_tf32(vv.w);
            *(float4*)&Vs[r * AV_STRIDE + g * 4] = t;
        }
        __syncthreads();

        // ---- S = Q K^T : float4 fragment loads, 2 k-steps per chunk ----
        float s[8][4];
#pragma unroll
        for (int nf = 0; nf < 8; nf++)
#pragma unroll
            for (int ci = 0; ci < 4; ci++) s[nf][ci] = 0.f;

#pragma unroll
        for (int cs = 0; cs < 4; cs++) {
            const float4 qlo = *(const float4*)&Qs[ar * AQ_STRIDE + cs * 16 + aoff];
            const float4 qhi = *(const float4*)&Qs[(ar + 8) * AQ_STRIDE + cs * 16 + aoff];
#pragma unroll
            for (int nf = 0; nf < 8; nf++) {
                const int kr = nf * 8 + qr;
                const float4 kb = *(const float4*)&Ks[kr * AQ_STRIDE + cs * 16 + ((qi ^ (kr & 3)) << 2)];
                mma_tf32(s[nf], qlo.x, qhi.x, qlo.y, qhi.y, kb.x, kb.y);
                mma_tf32(s[nf], qlo.z, qhi.z, qlo.w, qhi.w, kb.z, kb.w);
            }
        }

        // causal mask on diagonal tile
        if (kt == qt) {
            const int r0 = w * 16 + qr, r1 = r0 + 8;
#pragma unroll
            for (int nf = 0; nf < 8; nf++) {
                const int cb = nf * 8 + 2 * qi;
                if (cb     > r0) s[nf][0] = -1e30f;
                if (cb + 1 > r0) s[nf][1] = -1e30f;
                if (cb     > r1) s[nf][2] = -1e30f;
                if (cb + 1 > r1) s[nf][3] = -1e30f;
            }
        }

        // ---- online softmax (base-2; quad reduce) ----
        float mx0 = -1e30f, mx1 = -1e30f;
#pragma unroll
        for (int nf = 0; nf < 8; nf++) {
            mx0 = fmaxf(mx0, fmaxf(s[nf][0], s[nf][1]));
            mx1 = fmaxf(mx1, fmaxf(s[nf][2], s[nf][3]));
        }
        mx0 = fmaxf(mx0, __shfl_xor_sync(0xffffffffu, mx0, 1));
        mx0 = fmaxf(mx0, __shfl_xor_sync(0xffffffffu, mx0, 2));
        mx1 = fmaxf(mx1, __shfl_xor_sync(0xffffffffu, mx1, 1));
        mx1 = fmaxf(mx1, __shfl_xor_sync(0xffffffffu, mx1, 2));

        const float mn0 = fmaxf(m0, mx0), mn1 = fmaxf(m1, mx1);
        const float cf0 = exp2f(m0 - mn0), cf1 = exp2f(m1 - mn1);
        m0 = mn0; m1 = mn1;

        float rs0 = 0.f, rs1 = 0.f;
#pragma unroll
        for (int nf = 0; nf < 8; nf++) {
            s[nf][0] = to_tf32(exp2f(s[nf][0] - mn0)); rs0 += s[nf][0];
            s[nf][1] = to_tf32(exp2f(s[nf][1] - mn0)); rs0 += s[nf][1];
            s[nf][2] = to_tf32(exp2f(s[nf][2] - mn1)); rs1 += s[nf][2];
            s[nf][3] = to_tf32(exp2f(s[nf][3] - mn1)); rs1 += s[nf][3];
        }
        rs0 += __shfl_xor_sync(0xffffffffu, rs0, 1);
        rs0 += __shfl_xor_sync(0xffffffffu, rs0, 2);
        rs1 += __shfl_xor_sync(0xffffffffu, rs1, 1);
        rs1 += __shfl_xor_sync(0xffffffffu, rs1, 2);
        l0 = l0 * cf0 + rs0;
        l1 = l1 * cf1 + rs1;
#pragma unroll
        for (int nf = 0; nf < 8; nf++) {
            o[nf][0] *= cf0; o[nf][1] *= cf0;
            o[nf][2] *= cf1; o[nf][3] *= cf1;
        }

        // ---- O += P V, P stays in registers: quad-shuffle C-frag -> A-frag ----
#pragma unroll
        for (int t = 0; t < 8; t++) {
            const float u0 = __shfl_sync(0xffffffffu, s[t][0], q2);
            const float u1 = __shfl_sync(0xffffffffu, s[t][1], q2);
            const float u2 = __shfl_sync(0xffffffffu, s[t][2], q2);
            const float u3 = __shfl_sync(0xffffffffu, s[t][3], q2);
            const float w0 = __shfl_sync(0xffffffffu, s[t][0], q2 + 2);
            const float w1 = __shfl_sync(0xffffffffu, s[t][1], q2 + 2);
            const float w2 = __shfl_sync(0xffffffffu, s[t][2], q2 + 2);
            const float w3 = __shfl_sync(0xffffffffu, s[t][3], q2 + 2);
            const bool hi = (qi & 1);
            const float a0 = hi ? u1 : u0;   // P[r0][t*8+qi]
            const float a1 = hi ? u3 : u2;   // P[r0+8][t*8+qi]
            const float a2 = hi ? w1 : w0;   // P[r0][t*8+qi+4]
            const float a3 = hi ? w3 : w2;   // P[r0+8][t*8+qi+4]
#pragma unroll
            for (int nf = 0; nf < 8; nf++) {
                const float b0 = Vs[(t * 8 + qi) * AV_STRIDE + nf * 8 + qr];
                const float b1 = Vs[(t * 8 + qi + 4) * AV_STRIDE + nf * 8 + qr];
                mma_tf32(o[nf], a0, a1, a2, a3, b0, b1);
            }
        }
    }

    // ---- normalize + write ctx [b, n, h*64+d] ----
    const int b_ = bh >> 4, h_ = bh & 15;
    const float inv0 = 1.f / l0, inv1 = 1.f / l1;
#pragma unroll
    for (int nf = 0; nf < 8; nf++) {
        const int n0 = qt * 64 + w * 16 + qr;
        const int cb = h_ * 64 + nf * 8 + 2 * qi;
        g_ctx[((size_t)(b_ * NN + n0)) * DMODEL + cb]         = o[nf][0] * inv0;
        g_ctx[((size_t)(b_ * NN + n0)) * DMODEL + cb + 1]     = o[nf][1] * inv0;
        g_ctx[((size_t)(b_ * NN + n0 + 8)) * DMODEL + cb]     = o[nf][2] * inv1;
        g_ctx[((size_t)(b_ * NN + n0 + 8)) * DMODEL + cb + 1] = o[nf][3] * inv1;
    }
}

// ---------------------------------------------------------------------------
extern "C" void kernel_launch(void* const* d_in, const int* in_sizes, int n_in,
                              void* d_out, int out_size)
{
    const float* x  = (const float*)d_in[0];
    const float* Wq = (const float*)d_in[1];
    const float* Wk = (const float*)d_in[2];
    const float* Wv = (const float*)d_in[3];
    const float* Wo = (const float*)d_in[4];
    const float* bo = (const float*)d_in[5];
    float* out = (float*)d_out;

    cudaFuncSetAttribute(gemm_tc, cudaFuncAttributeMaxDynamicSharedMemorySize, GEMM_SMEM);
    cudaFuncSetAttribute(attn_tc, cudaFuncAttributeMaxDynamicSharedMemorySize, ATTN_SMEM);

    // QKV projections -> g_q/g_k/g_v [b,h,n,d]
    gemm_tc<<<dim3(4, 64, 3), 256, GEMM_SMEM>>>(x, Wq, Wk, Wv, nullptr, nullptr, 0);
    // causal flash attention
    attn_tc<<<dim3(32, 64), 128, ATTN_SMEM>>>();
    // output projection + bias
    gemm_tc<<<dim3(4, 64, 1), 256, GEMM_SMEM>>>(nullptr, Wo, nullptr, nullptr, bo, out, 1);
}

// round 10
// speedup vs baseline: 1.1672x; 1.1672x over previous
#include <cuda_runtime.h>
#include <cstdint>

#define D_IN   1024
#define DMODEL 1024
#define BB     4
#define NN     2048
#define NH     16
#define HD     64
#define MTOT   (BB*NN)   // 8192

// Scratch (device globals: allocation-free rule)
__device__ float g_xr[(size_t)MTOT*D_IN];          // X, tf32-rounded, k-permuted per row
__device__ float g_wr[(size_t)4*D_IN*DMODEL];      // Wq,Wk,Wv,Wo tf32-rounded
__device__ float g_q[(size_t)BB*NH*NN*HD];         // rounded, scaled, d-permuted
__device__ float g_k[(size_t)BB*NH*NN*HD];         // rounded, d-permuted
__device__ float g_v[(size_t)BB*NH*NN*HD];         // rounded, plain
__device__ float g_ctx[(size_t)MTOT*DMODEL];       // rounded, k-permuted per row

__device__ __forceinline__ float to_tf32(float x) {
    float r;
    asm("cvt.rna.tf32.f32 %0, %1;" : "=f"(r) : "f"(x));
    return r;
}

__device__ __forceinline__ void mma_tf32(float c[4], float a0, float a1, float a2, float a3,
                                         float b0, float b1) {
    asm("mma.sync.aligned.m16n8k8.row.col.f32.tf32.tf32.f32 "
        "{%0,%1,%2,%3},{%4,%5,%6,%7},{%8,%9},{%0,%1,%2,%3};"
        : "+f"(c[0]), "+f"(c[1]), "+f"(c[2]), "+f"(c[3])
        : "r"(__float_as_uint(a0)), "r"(__float_as_uint(a1)),
          "r"(__float_as_uint(a2)), "r"(__float_as_uint(a3)),
          "r"(__float_as_uint(b0)), "r"(__float_as_uint(b1)));
}

__device__ __forceinline__ void cp16(uint32_t s, const float* g) {
    asm volatile("cp.async.cg.shared.global [%0], [%1], 16;" :: "r"(s), "l"(g) : "memory");
}
#define CP_COMMIT() asm volatile("cp.async.commit_group;" ::: "memory")
#define CP_WAIT2()  asm volatile("cp.async.wait_group 2;" ::: "memory")
#define CP_WAIT0()  asm volatile("cp.async.wait_group 0;" ::: "memory")

// ---------------------------------------------------------------------------
// Prep: round to tf32 once. X additionally gets the k-within-16 permutation
// (keyed by row&3) so cp.async tile copies land in MMA-fragment order:
// element k=4g+j of row r is stored at p = 4*(j^(r&3)) + g within its 16-block.
// ---------------------------------------------------------------------------
__global__ __launch_bounds__(256)
void prep_x(const float* __restrict__ x)
{
    const int idx = blockIdx.x * 256 + threadIdx.x;
    const int r = idx >> 10, c = idx & 1023;
    const int base = c & ~15, p = c & 15;
    const int g = p & 3, j = (p >> 2) ^ (r & 3);
    g_xr[idx] = to_tf32(x[(r << 10) + base + (g << 2) + j]);
}

__global__ __launch_bounds__(256)
void prep_w(const float* __restrict__ w, int slot)
{
    const int idx = blockIdx.x * 256 + threadIdx.x;
    g_wr[(size_t)slot * D_IN * DMODEL + idx] = to_tf32(w[idx]);
}

// ---------------------------------------------------------------------------
// TF32 GEMM, cp.async 4-stage. CTA 128x128, 8 warps (2m x 4n), warp 64x32.
// A pre-permuted -> each thread's A-frags for two k-steps = one LDS.128.
// B plain [k][n] stride 136 (conflict-free scalar frag loads). Zero cvts,
// zero register prefetch, one barrier per k-tile.
// mode 0: A=g_xr, W=g_wr[z], out -> g_q/g_k/g_v (rounded; q scaled; q/k perm)
// mode 1: A=g_ctx, W=g_wr[3], out = A@W + bias
// ---------------------------------------------------------------------------
#define GS        4
#define GA_ST     (128*16)       // 2048 floats / stage
#define GB_STRIDE 136
#define GB_ST     (16*GB_STRIDE) // 2176 floats / stage
#define GEMM_SMEM ((GS*GA_ST + GS*GB_ST) * 4)   // 67584 B

__global__ __launch_bounds__(256, 2)
void gemm_tc(const float* __restrict__ bias,
             float* __restrict__ outp,
             int mode)
{
    extern __shared__ float smg[];
    float* As = smg;
    float* Bs = smg + GS * GA_ST;

    const int tid  = threadIdx.x;
    const int lane = tid & 31;
    const int warp = tid >> 5;
    const int wm   = warp >> 2;
    const int wn   = warp & 3;
    const int qr   = lane >> 2;
    const int qi   = lane & 3;
    const int bx   = blockIdx.x;
    const int by   = blockIdx.y;
    const int z    = blockIdx.z;

    const float* A = (mode == 0) ? g_xr : g_ctx;
    const float* W = g_wr + (size_t)((mode == 0) ? z : 3) * D_IN * DMODEL;
    const float* Abase = A + (size_t)by * 128 * D_IN;
    const float* Bbase = W + bx * 128;

    // cp.async chunk indices (2 A + 2 B per thread per stage)
    const int aR0 = tid >> 2,         aC0 = (tid & 3) * 4;
    const int aR1 = (tid + 256) >> 2, aC1 = aC0;
    const int bK0 = tid >> 5,         bN0 = (tid & 31) * 4;
    const int bK1 = (tid + 256) >> 5, bN1 = bN0;

    const uint32_t sA = (uint32_t)__cvta_generic_to_shared(As);
    const uint32_t sB = (uint32_t)__cvta_generic_to_shared(Bs);

    float c[4][4][4];
#pragma unroll
    for (int mf = 0; mf < 4; mf++)
#pragma unroll
        for (int nf = 0; nf < 4; nf++)
#pragma unroll
            for (int k = 0; k < 4; k++) c[mf][nf][k] = 0.f;

    auto issue = [&](int kt, int st) {
        const uint32_t a = sA + st * (GA_ST * 4);
        cp16(a + (aR0 * 16 + aC0) * 4, Abase + (size_t)aR0 * D_IN + kt * 16 + aC0);
        cp16(a + (aR1 * 16 + aC1) * 4, Abase + (size_t)aR1 * D_IN + kt * 16 + aC1);
        const uint32_t b = sB + st * (GB_ST * 4);
        cp16(b + (bK0 * GB_STRIDE + bN0) * 4, Bbase + (size_t)(kt * 16 + bK0) * DMODEL + bN0);
        cp16(b + (bK1 * GB_STRIDE + bN1) * 4, Bbase + (size_t)(kt * 16 + bK1) * DMODEL + bN1);
    };

    const int KT = D_IN / 16;  // 64
#pragma unroll
    for (int s = 0; s < GS - 1; s++) { issue(s, s); CP_COMMIT(); }

    const int aoff = ((qi ^ (qr & 3)) << 2);   // r0&3 == qr&3 for all frag rows

    for (int kt = 0; kt < KT; kt++) {
        CP_WAIT2();
        __syncthreads();
        const int kn = kt + GS - 1;
        if (kn < KT) issue(kn, kn & (GS - 1));
        CP_COMMIT();

        const float* Ab = As + (kt & (GS - 1)) * GA_ST;
        const float* Bb = Bs + (kt & (GS - 1)) * GB_ST;

        float4 fal[4], fah[4];
#pragma unroll
        for (int mf = 0; mf < 4; mf++) {
            const int r0 = wm * 64 + mf * 16 + qr;
            fal[mf] = *(const float4*)&Ab[r0 * 16 + aoff];
            fah[mf] = *(const float4*)&Ab[(r0 + 8) * 16 + aoff];
        }
#pragma unroll
        for (int ks = 0; ks < 2; ks++) {
            float b0[4], b1[4];
#pragma unroll
            for (int nf = 0; nf < 4; nf++) {
                const int cB = wn * 32 + nf * 8 + qr;
                b0[nf] = Bb[(ks * 8 + qi) * GB_STRIDE + cB];
                b1[nf] = Bb[(ks * 8 + qi + 4) * GB_STRIDE + cB];
            }
#pragma unroll
            for (int mf = 0; mf < 4; mf++) {
                const float a0 = ks ? fal[mf].z : fal[mf].x;
                const float a1 = ks ? fah[mf].z : fah[mf].x;
                const float a2 = ks ? fal[mf].w : fal[mf].y;
                const float a3 = ks ? fah[mf].w : fah[mf].y;
#pragma unroll
                for (int nf = 0; nf < 4; nf++)
                    mma_tf32(c[mf][nf], a0, a1, a2, a3, b0[nf], b1[nf]);
            }
        }
    }

    // ---- epilogue ----
    if (mode == 0) {
        float* O = (z == 0) ? g_q : (z == 1) ? g_k : g_v;
        const float mult = (z == 0) ? (0.125f * 1.44269504088896f) : 1.f;  // 1/sqrt(64)*log2e
        const int xkey = qr & 3;   // == m&3
#pragma unroll
        for (int mf = 0; mf < 4; mf++)
#pragma unroll
            for (int nf = 0; nf < 4; nf++)
#pragma unroll
                for (int ci = 0; ci < 4; ci++) {
                    const int m   = by * 128 + wm * 64 + mf * 16 + qr + ((ci >= 2) ? 8 : 0);
                    const int col = bx * 128 + wn * 32 + nf * 8 + 2 * qi + (ci & 1);
                    const int b_ = m >> 11, n_ = m & (NN - 1);
                    const int h_ = col >> 6, d = col & (HD - 1);
                    int dd = d;
                    if (z != 2) {  // q/k stored in attention's permuted fragment layout
                        const int dl = d & 15, gg = dl >> 2, j = dl & 3;
                        dd = (d & ~15) | ((j ^ xkey) << 2) | gg;
                    }
                    O[(((size_t)(b_ * NH + h_)) * NN + n_) * HD + dd] = to_tf32(c[mf][nf][ci] * mult);
                }
    } else {
#pragma unroll
        for (int mf = 0; mf < 4; mf++)
#pragma unroll
            for (int nf = 0; nf < 4; nf++)
#pragma unroll
                for (int ci = 0; ci < 4; ci++) {
                    const int m   = by * 128 + wm * 64 + mf * 16 + qr + ((ci >= 2) ? 8 : 0);
                    const int col = bx * 128 + wn * 32 + nf * 8 + 2 * qi + (ci & 1);
                    outp[(size_t)m * DMODEL + col] = c[mf][nf][ci] + bias[col];
                }
    }
}

// ---------------------------------------------------------------------------
// Flash attention (causal). 128 thr = 4 warps x 16 q-rows. Inputs pre-rounded
// (Q pre-scaled) by gemm epilogue; Q/K pre-permuted -> float4 fragment LDS.
// K/V tiles double-buffered via cp.async (latency overlapped with MMAs),
// ONE barrier per kt-tile. P stays in registers via quad shuffles.
// ---------------------------------------------------------------------------
#define AK_STRIDE 80
#define AV_STRIDE 68
#define ATTN_SMEM ((64*AK_STRIDE + 2*64*AK_STRIDE + 2*64*AV_STRIDE) * 4)  // 96256 B

__global__ __launch_bounds__(128, 2)
void attn_tc()
{
    extern __shared__ float sm[];
    float* Qs = sm;                              // [64][80]
    float* Ks = sm + 64 * AK_STRIDE;             // [2][64][80]
    float* Vs = Ks + 2 * 64 * AK_STRIDE;         // [2][64][68]

    const int tid  = threadIdx.x;
    const int lane = tid & 31;
    const int w    = tid >> 5;
    const int qr   = lane >> 2;
    const int qi   = lane & 3;
    const int qt   = 31 - blockIdx.x;            // longest CTAs first
    const int bh   = blockIdx.y;

    const float* Qg = g_q + ((size_t)bh * NN + qt * 64) * HD;
    const float* Kg = g_k + (size_t)bh * NN * HD;
    const float* Vg = g_v + (size_t)bh * NN * HD;

    const uint32_t sK = (uint32_t)__cvta_generic_to_shared(Ks);
    const uint32_t sV = (uint32_t)__cvta_generic_to_shared(Vs);

    auto issueKV = [&](int kt, int buf) {
        const float* Ktg = Kg + (size_t)kt * 64 * HD;
        const float* Vtg = Vg + (size_t)kt * 64 * HD;
#pragma unroll
        for (int l = 0; l < 8; l++) {
            const int idx = l * 128 + tid;
            const int r = idx >> 4, cc = (idx & 15) * 4;
            cp16(sK + (buf * 64 * AK_STRIDE + r * AK_STRIDE + cc) * 4, Ktg + r * 64 + cc);
            cp16(sV + (buf * 64 * AV_STRIDE + r * AV_STRIDE + cc) * 4, Vtg + r * 64 + cc);
        }
    };

    issueKV(0, 0);
    CP_COMMIT();

    // Q tile: straight float4 copy (already permuted + scaled + rounded)
#pragma unroll
    for (int p = 0; p < 8; p++) {
        const int idx = p * 128 + tid;
        const int r = idx >> 4, cc = (idx & 15) * 4;
        *(float4*)&Qs[r * AK_STRIDE + cc] = *(const float4*)(Qg + r * 64 + cc);
    }

    float m0 = -1e30f, m1 = -1e30f, l0 = 0.f, l1 = 0.f;
    float o[8][4];
#pragma unroll
    for (int nf = 0; nf < 8; nf++)
#pragma unroll
        for (int ci = 0; ci < 4; ci++) o[nf][ci] = 0.f;

    const int ar   = w * 16 + qr;
    const int aoff = ((qi ^ (qr & 3)) << 2);
    const int q2   = (lane & 28) | (qi >> 1);

    for (int kt = 0; kt <= qt; kt++) {
        CP_WAIT0();
        __syncthreads();                 // tile kt visible; all warps past kt-1 compute
        if (kt < qt) issueKV(kt + 1, (kt + 1) & 1);
        CP_COMMIT();

        const float* Kb = Ks + (kt & 1) * 64 * AK_STRIDE;
        const float* Vb = Vs + (kt & 1) * 64 * AV_STRIDE;

        // ---- S = Q K^T ----
        float s[8][4];
#pragma unroll
        for (int nf = 0; nf < 8; nf++)
#pragma unroll
            for (int ci = 0; ci < 4; ci++) s[nf][ci] = 0.f;

#pragma unroll
        for (int cs = 0; cs < 4; cs++) {
            const float4 qlo = *(const float4*)&Qs[ar * AK_STRIDE + cs * 16 + aoff];
            const float4 qhi = *(const float4*)&Qs[(ar + 8) * AK_STRIDE + cs * 16 + aoff];
#pragma unroll
            for (int nf = 0; nf < 8; nf++) {
                const int kr = nf * 8 + qr;
                const float4 kb = *(const float4*)&Kb[kr * AK_STRIDE + cs * 16 + aoff];
                mma_tf32(s[nf], qlo.x, qhi.x, qlo.y, qhi.y, kb.x, kb.y);
                mma_tf32(s[nf], qlo.z, qhi.z, qlo.w, qhi.w, kb.z, kb.w);
            }
        }

        if (kt == qt) {
            const int r0 = w * 16 + qr, r1 = r0 + 8;
#pragma unroll
            for (int nf = 0; nf < 8; nf++) {
                const int cb = nf * 8 + 2 * qi;
                if (cb     > r0) s[nf][0] = -1e30f;
                if (cb + 1 > r0) s[nf][1] = -1e30f;
                if (cb     > r1) s[nf][2] = -1e30f;
                if (cb + 1 > r1) s[nf][3] = -1e30f;
            }
        }

        // ---- online softmax (base-2, quad reduce) ----
        float mx0 = -1e30f, mx1 = -1e30f;
#pragma unroll
        for (int nf = 0; nf < 8; nf++) {
            mx0 = fmaxf(mx0, fmaxf(s[nf][0], s[nf][1]));
            mx1 = fmaxf(mx1, fmaxf(s[nf][2], s[nf][3]));
        }
        mx0 = fmaxf(mx0, __shfl_xor_sync(0xffffffffu, mx0, 1));
        mx0 = fmaxf(mx0, __shfl_xor_sync(0xffffffffu, mx0, 2));
        mx1 = fmaxf(mx1, __shfl_xor_sync(0xffffffffu, mx1, 1));
        mx1 = fmaxf(mx1, __shfl_xor_sync(0xffffffffu, mx1, 2));

        const float mn0 = fmaxf(m0, mx0), mn1 = fmaxf(m1, mx1);
        const float cf0 = exp2f(m0 - mn0), cf1 = exp2f(m1 - mn1);
        m0 = mn0; m1 = mn1;

        float rs0 = 0.f, rs1 = 0.f;
#pragma unroll
        for (int nf = 0; nf < 8; nf++) {
            s[nf][0] = to_tf32(exp2f(s[nf][0] - mn0)); rs0 += s[nf][0];
            s[nf][1] = to_tf32(exp2f(s[nf][1] - mn0)); rs0 += s[nf][1];
            s[nf][2] = to_tf32(exp2f(s[nf][2] - mn1)); rs1 += s[nf][2];
            s[nf][3] = to_tf32(exp2f(s[nf][3] - mn1)); rs1 += s[nf][3];
        }
        rs0 += __shfl_xor_sync(0xffffffffu, rs0, 1);
        rs0 += __shfl_xor_sync(0xffffffffu, rs0, 2);
        rs1 += __shfl_xor_sync(0xffffffffu, rs1, 1);
        rs1 += __shfl_xor_sync(0xffffffffu, rs1, 2);
        l0 = l0 * cf0 + rs0;
        l1 = l1 * cf1 + rs1;
#pragma unroll
        for (int nf = 0; nf < 8; nf++) {
            o[nf][0] *= cf0; o[nf][1] *= cf0;
            o[nf][2] *= cf1; o[nf][3] *= cf1;
        }

        // ---- O += P V (P in registers via quad shuffles) ----
#pragma unroll
        for (int t = 0; t < 8; t++) {
            const float u0 = __shfl_sync(0xffffffffu, s[t][0], q2);
            const float u1 = __shfl_sync(0xffffffffu, s[t][1], q2);
            const float u2 = __shfl_sync(0xffffffffu, s[t][2], q2);
            const float u3 = __shfl_sync(0xffffffffu, s[t][3], q2);
            const float w0 = __shfl_sync(0xffffffffu, s[t][0], q2 + 2);
            const float w1 = __shfl_sync(0xffffffffu, s[t][1], q2 + 2);
            const float w2 = __shfl_sync(0xffffffffu, s[t][2], q2 + 2);
            const float w3 = __shfl_sync(0xffffffffu, s[t][3], q2 + 2);
            const bool hi = (qi & 1);
            const float a0 = hi ? u1 : u0;
            const float a1 = hi ? u3 : u2;
            const float a2 = hi ? w1 : w0;
            const float a3 = hi ? w3 : w2;
#pragma unroll
            for (int nf = 0; nf < 8; nf++) {
                const float b0 = Vb[(t * 8 + qi) * AV_STRIDE + nf * 8 + qr];
                const float b1 = Vb[(t * 8 + qi + 4) * AV_STRIDE + nf * 8 + qr];
                mma_tf32(o[nf], a0, a1, a2, a3, b0, b1);
            }
        }
    }

    // ---- normalize + write ctx (rounded, k-permuted for out-proj GEMM) ----
    const int b_ = bh >> 4, h_ = bh & 15;
    const int xkey = qr & 3;
    const float inv0 = 1.f / l0, inv1 = 1.f / l1;
#pragma unroll
    for (int nf = 0; nf < 8; nf++) {
        const int n0 = qt * 64 + w * 16 + qr;
        const int cb = h_ * 64 + nf * 8 + 2 * qi;
        const int cl = cb & 15, gg = cl >> 2, j0 = cl & 3;
        const int c0 = (cb & ~15) | ((j0 ^ xkey) << 2) | gg;
        const int c1 = (cb & ~15) | (((j0 + 1) ^ xkey) << 2) | gg;
        const size_t row0 = (size_t)(b_ * NN + n0) * DMODEL;
        const size_t row1 = (size_t)(b_ * NN + n0 + 8) * DMODEL;
        g_ctx[row0 + c0] = to_tf32(o[nf][0] * inv0);
        g_ctx[row0 + c1] = to_tf32(o[nf][1] * inv0);
        g_ctx[row1 + c0] = to_tf32(o[nf][2] * inv1);
        g_ctx[row1 + c1] = to_tf32(o[nf][3] * inv1);
    }
}

// ---------------------------------------------------------------------------
extern "C" void kernel_launch(void* const* d_in, const int* in_sizes, int n_in,
                              void* d_out, int out_size)
{
    const float* x  = (const float*)d_in[0];
    const float* Wq = (const float*)d_in[1];
    const float* Wk = (const float*)d_in[2];
    const float* Wv = (const float*)d_in[3];
    const float* Wo = (const float*)d_in[4];
    const float* bo = (const float*)d_in[5];
    float* out = (float*)d_out;

    cudaFuncSetAttribute(gemm_tc, cudaFuncAttributeMaxDynamicSharedMemorySize, GEMM_SMEM);
    cudaFuncSetAttribute(attn_tc, cudaFuncAttributeMaxDynamicSharedMemorySize, ATTN_SMEM);

    // one-time tf32 rounding (+ X permutation)
    prep_x<<<(MTOT * D_IN) / 256, 256>>>(x);
    prep_w<<<(D_IN * DMODEL) / 256, 256>>>(Wq, 0);
    prep_w<<<(D_IN * DMODEL) / 256, 256>>>(Wk, 1);
    prep_w<<<(D_IN * DMODEL) / 256, 256>>>(Wv, 2);
    prep_w<<<(D_IN * DMODEL) / 256, 256>>>(Wo, 3);

    // QKV projections -> g_q/g_k/g_v
    gemm_tc<<<dim3(8, 64, 3), 256, GEMM_SMEM>>>(nullptr, nullptr, 0);
    // causal flash attention
    attn_tc<<<dim3(32, 64), 128, ATTN_SMEM>>>();
    // output projection + bias
    gemm_tc<<<dim3(8, 64, 1), 256, GEMM_SMEM>>>(bo, out, 1);
}

// round 11
// speedup vs baseline: 1.2361x; 1.0591x over previous
#include <cuda_runtime.h>
#include <cstdint>

#define D_IN   1024
#define DMODEL 1024
#define BB     4
#define NN     2048
#define NH     16
#define HD     64
#define MTOT   (BB*NN)   // 8192

// Scratch (device globals: allocation-free rule)
__device__ float g_xr[(size_t)MTOT*D_IN];        // X tf32, k-permuted per row
__device__ float g_wt[(size_t)4*DMODEL*D_IN];    // W^T tf32, k-permuted per col-row
__device__ float g_q[(size_t)BB*NH*NN*HD];       // tf32, scaled, d-permuted
__device__ float g_k[(size_t)BB*NH*NN*HD];       // tf32, d-permuted
__device__ float g_v[(size_t)BB*NH*HD*NN];       // tf32, TRANSPOSED [bh][d][n], n-permuted
__device__ float g_ctx[(size_t)MTOT*DMODEL];     // tf32, k-permuted per row

__device__ __forceinline__ float to_tf32(float x) {
    float r;
    asm("cvt.rna.tf32.f32 %0, %1;" : "=f"(r) : "f"(x));
    return r;
}

__device__ __forceinline__ void mma_tf32(float c[4], float a0, float a1, float a2, float a3,
                                         float b0, float b1) {
    asm("mma.sync.aligned.m16n8k8.row.col.f32.tf32.tf32.f32 "
        "{%0,%1,%2,%3},{%4,%5,%6,%7},{%8,%9},{%0,%1,%2,%3};"
        : "+f"(c[0]), "+f"(c[1]), "+f"(c[2]), "+f"(c[3])
        : "r"(__float_as_uint(a0)), "r"(__float_as_uint(a1)),
          "r"(__float_as_uint(a2)), "r"(__float_as_uint(a3)),
          "r"(__float_as_uint(b0)), "r"(__float_as_uint(b1)));
}

__device__ __forceinline__ void cp16(uint32_t s, const float* g) {
    asm volatile("cp.async.cg.shared.global [%0], [%1], 16;" :: "r"(s), "l"(g) : "memory");
}
#define CP_COMMIT() asm volatile("cp.async.commit_group;" ::: "memory")
#define CP_WAIT2()  asm volatile("cp.async.wait_group 2;" ::: "memory")
#define CP_WAIT0()  asm volatile("cp.async.wait_group 0;" ::: "memory")

// ---------------------------------------------------------------------------
// Prep. X: tf32 + k-within-16 permutation keyed by row&3 (element k=4g+j of
// row r stored at p = 4*(j^(r&3)) + g). W: transpose to [n][k], tf32, same
// k-permutation keyed by n&3 (tiled smem transpose, both sides coalesced).
// ---------------------------------------------------------------------------
__global__ __launch_bounds__(256)
void prep_x(const float* __restrict__ x)
{
    const int idx = blockIdx.x * 256 + threadIdx.x;
    const int r = idx >> 10, c = idx & 1023;
    const int base = c & ~15, p = c & 15;
    const int g = p & 3, j = (p >> 2) ^ (r & 3);
    g_xr[idx] = to_tf32(x[(r << 10) + base + (g << 2) + j]);
}

__global__ __launch_bounds__(256)
void prep_wt(const float* __restrict__ w, int slot)
{
    __shared__ float t[32][33];
    const int tx = threadIdx.x & 31, ty = threadIdx.x >> 5;  // 32 x 8
    const int n0 = blockIdx.x * 32, k0 = blockIdx.y * 32;
#pragma unroll
    for (int i = 0; i < 4; i++)
        t[ty + 8 * i][tx] = w[(size_t)(k0 + ty + 8 * i) * DMODEL + n0 + tx];
    __syncthreads();
    float* dst = g_wt + (size_t)slot * DMODEL * D_IN;
#pragma unroll
    for (int i = 0; i < 4; i++) {
        const int n = n0 + ty + 8 * i;
        const int kk = tx;  // local k in 0..31
        const int pos = (kk & 16) | (4 * ((kk & 3) ^ (n & 3))) | ((kk >> 2) & 3);
        dst[(size_t)n * D_IN + k0 + pos] = to_tf32(t[kk][ty + 8 * i]);
    }
}

// ---------------------------------------------------------------------------
// TF32 GEMM, cp.async 4-stage. CTA 128x128, 8 warps (2m x 4n), warp 64x32.
// BOTH operands pre-permuted: A-frags (2 k-steps) = 1 LDS.128; B-frags
// (2 k-steps) = 1 LDS.128. 12 vector LDS + 32 MMA per warp-ktile, zero cvts.
// mode 0: A=g_xr, B=g_wt[z], out -> g_q/g_k (frag layout) / g_v (transposed)
// mode 1: A=g_ctx, B=g_wt[3], out = A@W + bias
// ---------------------------------------------------------------------------
#define GS      4
#define G_ST    (128*16)                      // floats per stage (A and B alike)
#define GEMM_SMEM ((2*GS*G_ST) * 4)           // 65536 B

__global__ __launch_bounds__(256, 2)
void gemm_tc(const float* __restrict__ bias,
             float* __restrict__ outp,
             int mode)
{
    extern __shared__ float smg[];
    float* As = smg;
    float* Bs = smg + GS * G_ST;

    const int tid  = threadIdx.x;
    const int lane = tid & 31;
    const int warp = tid >> 5;
    const int wm   = warp >> 2;
    const int wn   = warp & 3;
    const int qr   = lane >> 2;
    const int qi   = lane & 3;
    const int bx   = blockIdx.x;
    const int by   = blockIdx.y;
    const int z    = blockIdx.z;

    const float* A = (mode == 0) ? g_xr : g_ctx;
    const float* Bt = g_wt + (size_t)((mode == 0) ? z : 3) * DMODEL * D_IN;
    const float* Abase = A + (size_t)by * 128 * D_IN;
    const float* Bbase = Bt + (size_t)(bx * 128) * D_IN;

    // cp.async: 2 A-chunks + 2 B-chunks per thread per stage (identical shape)
    const int aR0 = tid >> 2,         aC0 = (tid & 3) * 4;
    const int aR1 = (tid + 256) >> 2, aC1 = aC0;

    const uint32_t sA = (uint32_t)__cvta_generic_to_shared(As);
    const uint32_t sB = (uint32_t)__cvta_generic_to_shared(Bs);

    float c[4][4][4];
#pragma unroll
    for (int mf = 0; mf < 4; mf++)
#pragma unroll
        for (int nf = 0; nf < 4; nf++)
#pragma unroll
            for (int k = 0; k < 4; k++) c[mf][nf][k] = 0.f;

    auto issue = [&](int kt, int st) {
        const uint32_t a = sA + st * (G_ST * 4);
        cp16(a + (aR0 * 16 + aC0) * 4, Abase + (size_t)aR0 * D_IN + kt * 16 + aC0);
        cp16(a + (aR1 * 16 + aC1) * 4, Abase + (size_t)aR1 * D_IN + kt * 16 + aC1);
        const uint32_t b = sB + st * (G_ST * 4);
        cp16(b + (aR0 * 16 + aC0) * 4, Bbase + (size_t)aR0 * D_IN + kt * 16 + aC0);
        cp16(b + (aR1 * 16 + aC1) * 4, Bbase + (size_t)aR1 * D_IN + kt * 16 + aC1);
    };

    const int KT = D_IN / 16;  // 64
#pragma unroll
    for (int s = 0; s < GS - 1; s++) { issue(s, s); CP_COMMIT(); }

    const int aoff = ((qi ^ (qr & 3)) << 2);

    for (int kt = 0; kt < KT; kt++) {
        CP_WAIT2();
        __syncthreads();
        const int kn = kt + GS - 1;
        if (kn < KT) issue(kn, kn & (GS - 1));
        CP_COMMIT();

        const float* Ab = As + (kt & (GS - 1)) * G_ST;
        const float* Bb = Bs + (kt & (GS - 1)) * G_ST;

        float4 fal[4], fah[4], fb[4];
#pragma unroll
        for (int mf = 0; mf < 4; mf++) {
            const int r0 = wm * 64 + mf * 16 + qr;
            fal[mf] = *(const float4*)&Ab[r0 * 16 + aoff];
            fah[mf] = *(const float4*)&Ab[(r0 + 8) * 16 + aoff];
        }
#pragma unroll
        for (int nf = 0; nf < 4; nf++) {
            const int n = wn * 32 + nf * 8 + qr;
            fb[nf] = *(const float4*)&Bb[n * 16 + aoff];
        }
        // fb: .x=b0(ks0) .y=b1(ks0) .z=b0(ks1) .w=b1(ks1)
#pragma unroll
        for (int ks = 0; ks < 2; ks++)
#pragma unroll
            for (int mf = 0; mf < 4; mf++) {
                const float a0 = ks ? fal[mf].z : fal[mf].x;
                const float a1 = ks ? fah[mf].z : fah[mf].x;
                const float a2 = ks ? fal[mf].w : fal[mf].y;
                const float a3 = ks ? fah[mf].w : fah[mf].y;
#pragma unroll
                for (int nf = 0; nf < 4; nf++)
                    mma_tf32(c[mf][nf], a0, a1, a2, a3,
                             ks ? fb[nf].z : fb[nf].x, ks ? fb[nf].w : fb[nf].y);
            }
    }

    // ---- epilogue ----
    if (mode == 0) {
#pragma unroll
        for (int mf = 0; mf < 4; mf++)
#pragma unroll
            for (int nf = 0; nf < 4; nf++)
#pragma unroll
                for (int ci = 0; ci < 4; ci++) {
                    const int m   = by * 128 + wm * 64 + mf * 16 + qr + ((ci >= 2) ? 8 : 0);
                    const int col = bx * 128 + wn * 32 + nf * 8 + 2 * qi + (ci & 1);
                    const int b_ = m >> 11, n_ = m & (NN - 1);
                    const int h_ = col >> 6, d = col & (HD - 1);
                    if (z == 2) {
                        // V transposed [bh][d][n], n-within-16 permuted keyed by d&3
                        const int nl = n_ & 15;
                        const int np = (n_ & ~15) | (4 * ((nl & 3) ^ (d & 3))) | (nl >> 2);
                        g_v[((size_t)(b_ * NH + h_) * HD + d) * NN + np] = to_tf32(c[mf][nf][ci]);
                    } else {
                        // Q/K in attention fragment layout: d-within-16 permuted by n&3
                        const float mult = (z == 0) ? (0.125f * 1.44269504088896f) : 1.f;
                        const int dl = d & 15, gg = dl >> 2, j = dl & 3;
                        const int dd = (d & ~15) | ((j ^ (n_ & 3)) << 2) | gg;
                        float* O = (z == 0) ? g_q : g_k;
                        O[(((size_t)(b_ * NH + h_)) * NN + n_) * HD + dd] =
                            to_tf32(c[mf][nf][ci] * mult);
                    }
                }
    } else {
#pragma unroll
        for (int mf = 0; mf < 4; mf++)
#pragma unroll
            for (int nf = 0; nf < 4; nf++)
#pragma unroll
                for (int ci = 0; ci < 4; ci++) {
                    const int m   = by * 128 + wm * 64 + mf * 16 + qr + ((ci >= 2) ? 8 : 0);
                    const int col = bx * 128 + wn * 32 + nf * 8 + 2 * qi + (ci & 1);
                    outp[(size_t)m * DMODEL + col] = c[mf][nf][ci] + bias[col];
                }
    }
}

// ---------------------------------------------------------------------------
// Flash attention (causal). 128 thr = 4 warps x 16 q-rows.
// Q fragments live in REGISTERS for the whole loop (direct LDG from the
// fragment-layout g_q). K and V^T tiles double-buffered via cp.async; all
// fragment loads are LDS.128 (K keyed by token&3, V^T keyed by d&3).
// P stays in registers via quad shuffles. One barrier per kt-tile.
// ---------------------------------------------------------------------------
#define AT_STRIDE 80
#define ATTN_SMEM ((2*64*AT_STRIDE + 2*64*AT_STRIDE) * 4)   // 81920 B

__global__ __launch_bounds__(128, 2)
void attn_tc()
{
    extern __shared__ float sm[];
    float* Ks = sm;                        // [2][64 tok][80]
    float* Vs = sm + 2 * 64 * AT_STRIDE;   // [2][64 d][80] (V^T, n-permuted)

    const int tid  = threadIdx.x;
    const int lane = tid & 31;
    const int w    = tid >> 5;
    const int qr   = lane >> 2;
    const int qi   = lane & 3;
    const int qt   = 31 - blockIdx.x;      // longest CTAs first
    const int bh   = blockIdx.y;

    const float* Qg = g_q + ((size_t)bh * NN + qt * 64) * HD;
    const float* Kg = g_k + (size_t)bh * NN * HD;
    const float* Vg = g_v + (size_t)bh * HD * NN;

    const uint32_t sK = (uint32_t)__cvta_generic_to_shared(Ks);
    const uint32_t sV = (uint32_t)__cvta_generic_to_shared(Vs);

    auto issueKV = [&](int kt, int buf) {
        const float* Ktg = Kg + (size_t)kt * 64 * HD;
        const float* Vtg = Vg + kt * 64;                 // token window in V^T rows
#pragma unroll
        for (int l = 0; l < 8; l++) {
            const int idx = l * 128 + tid;
            const int r = idx >> 4, cc = (idx & 15) * 4;
            cp16(sK + (buf * 64 * AT_STRIDE + r * AT_STRIDE + cc) * 4, Ktg + r * 64 + cc);
            cp16(sV + (buf * 64 * AT_STRIDE + r * AT_STRIDE + cc) * 4, Vtg + (size_t)r * NN + cc);
        }
    };

    issueKV(0, 0);
    CP_COMMIT();

    const int ar   = w * 16 + qr;
    const int aoff = ((qi ^ (qr & 3)) << 2);
    const int q2   = (lane & 28) | (qi >> 1);

    // Q fragments for the whole loop: 8 LDG.128 (g_q already fragment-ordered)
    float4 ql[4], qh[4];
#pragma unroll
    for (int cs = 0; cs < 4; cs++) {
        ql[cs] = *(const float4*)(Qg + ar * 64 + cs * 16 + aoff);
        qh[cs] = *(const float4*)(Qg + (ar + 8) * 64 + cs * 16 + aoff);
    }

    float m0 = -1e30f, m1 = -1e30f, l0 = 0.f, l1 = 0.f;
    float o[8][4];
#pragma unroll
    for (int nf = 0; nf < 8; nf++)
#pragma unroll
        for (int ci = 0; ci < 4; ci++) o[nf][ci] = 0.f;

    for (int kt = 0; kt <= qt; kt++) {
        CP_WAIT0();
        __syncthreads();
        if (kt < qt) issueKV(kt + 1, (kt + 1) & 1);
        CP_COMMIT();

        const float* Kb = Ks + (kt & 1) * 64 * AT_STRIDE;
        const float* Vb = Vs + (kt & 1) * 64 * AT_STRIDE;

        // ---- S = Q K^T ----
        float s[8][4];
#pragma unroll
        for (int nf = 0; nf < 8; nf++)
#pragma unroll
            for (int ci = 0; ci < 4; ci++) s[nf][ci] = 0.f;

#pragma unroll
        for (int cs = 0; cs < 4; cs++) {
#pragma unroll
            for (int nf = 0; nf < 8; nf++) {
                const int kr = nf * 8 + qr;
                const float4 kb = *(const float4*)&Kb[kr * AT_STRIDE + cs * 16 + aoff];
                mma_tf32(s[nf], ql[cs].x, qh[cs].x, ql[cs].y, qh[cs].y, kb.x, kb.y);
                mma_tf32(s[nf], ql[cs].z, qh[cs].z, ql[cs].w, qh[cs].w, kb.z, kb.w);
            }
        }

        if (kt == qt) {
            const int r0 = w * 16 + qr, r1 = r0 + 8;
#pragma unroll
            for (int nf = 0; nf < 8; nf++) {
                const int cb = nf * 8 + 2 * qi;
                if (cb     > r0) s[nf][0] = -1e30f;
                if (cb + 1 > r0) s[nf][1] = -1e30f;
                if (cb     > r1) s[nf][2] = -1e30f;
                if (cb + 1 > r1) s[nf][3] = -1e30f;
            }
        }

        // ---- online softmax (base-2, quad reduce) ----
        float mx0 = -1e30f, mx1 = -1e30f;
#pragma unroll
        for (int nf = 0; nf < 8; nf++) {
            mx0 = fmaxf(mx0, fmaxf(s[nf][0], s[nf][1]));
            mx1 = fmaxf(mx1, fmaxf(s[nf][2], s[nf][3]));
        }
        mx0 = fmaxf(mx0, __shfl_xor_sync(0xffffffffu, mx0, 1));
        mx0 = fmaxf(mx0, __shfl_xor_sync(0xffffffffu, mx0, 2));
        mx1 = fmaxf(mx1, __shfl_xor_sync(0xffffffffu, mx1, 1));
        mx1 = fmaxf(mx1, __shfl_xor_sync(0xffffffffu, mx1, 2));

        const float mn0 = fmaxf(m0, mx0), mn1 = fmaxf(m1, mx1);
        const float cf0 = exp2f(m0 - mn0), cf1 = exp2f(m1 - mn1);
        m0 = mn0; m1 = mn1;

        float rs0 = 0.f, rs1 = 0.f;
#pragma unroll
        for (int nf = 0; nf < 8; nf++) {
            s[nf][0] = to_tf32(exp2f(s[nf][0] - mn0)); rs0 += s[nf][0];
            s[nf][1] = to_tf32(exp2f(s[nf][1] - mn0)); rs0 += s[nf][1];
            s[nf][2] = to_tf32(exp2f(s[nf][2] - mn1)); rs1 += s[nf][2];
            s[nf][3] = to_tf32(exp2f(s[nf][3] - mn1)); rs1 += s[nf][3];
        }
        rs0 += __shfl_xor_sync(0xffffffffu, rs0, 1);
        rs0 += __shfl_xor_sync(0xffffffffu, rs0, 2);
        rs1 += __shfl_xor_sync(0xffffffffu, rs1, 1);
        rs1 += __shfl_xor_sync(0xffffffffu, rs1, 2);
        l0 = l0 * cf0 + rs0;
        l1 = l1 * cf1 + rs1;
#pragma unroll
        for (int nf = 0; nf < 8; nf++) {
            o[nf][0] *= cf0; o[nf][1] *= cf0;
            o[nf][2] *= cf1; o[nf][3] *= cf1;
        }

        // ---- P: C-frag -> A-frag via quad shuffles (registers only) ----
        float pa[8][4];
#pragma unroll
        for (int t = 0; t < 8; t++) {
            const float u0 = __shfl_sync(0xffffffffu, s[t][0], q2);
            const float u1 = __shfl_sync(0xffffffffu, s[t][1], q2);
            const float u2 = __shfl_sync(0xffffffffu, s[t][2], q2);
            const float u3 = __shfl_sync(0xffffffffu, s[t][3], q2);
            const float w0 = __shfl_sync(0xffffffffu, s[t][0], q2 + 2);
            const float w1 = __shfl_sync(0xffffffffu, s[t][1], q2 + 2);
            const float w2 = __shfl_sync(0xffffffffu, s[t][2], q2 + 2);
            const float w3 = __shfl_sync(0xffffffffu, s[t][3], q2 + 2);
            const bool hi = (qi & 1);
            pa[t][0] = hi ? u1 : u0;
            pa[t][1] = hi ? u3 : u2;
            pa[t][2] = hi ? w1 : w0;
            pa[t][3] = hi ? w3 : w2;
        }

        // ---- O += P V : V^T fragments are LDS.128 (2 k-steps each) ----
#pragma unroll
        for (int cs = 0; cs < 4; cs++) {
#pragma unroll
            for (int nf = 0; nf < 8; nf++) {
                const int dr = nf * 8 + qr;
                const float4 vb = *(const float4*)&Vb[dr * AT_STRIDE + cs * 16 + aoff];
                mma_tf32(o[nf], pa[2*cs][0], pa[2*cs][1], pa[2*cs][2], pa[2*cs][3], vb.x, vb.y);
                mma_tf32(o[nf], pa[2*cs+1][0], pa[2*cs+1][1], pa[2*cs+1][2], pa[2*cs+1][3], vb.z, vb.w);
            }
        }
    }

    // ---- normalize + write ctx (tf32, k-permuted for out-proj A side) ----
    const int b_ = bh >> 4, h_ = bh & 15;
    const int xkey = qr & 3;
    const float inv0 = 1.f / l0, inv1 = 1.f / l1;
#pragma unroll
    for (int nf = 0; nf < 8; nf++) {
        const int n0 = qt * 64 + w * 16 + qr;
        const int cb = h_ * 64 + nf * 8 + 2 * qi;
        const int cl = cb & 15, gg = cl >> 2, j0 = cl & 3;
        const int c0 = (cb & ~15) | ((j0 ^ xkey) << 2) | gg;
        const int c1 = (cb & ~15) | (((j0 + 1) ^ xkey) << 2) | gg;
        const size_t row0 = (size_t)(b_ * NN + n0) * DMODEL;
        const size_t row1 = (size_t)(b_ * NN + n0 + 8) * DMODEL;
        g_ctx[row0 + c0] = to_tf32(o[nf][0] * inv0);
        g_ctx[row0 + c1] = to_tf32(o[nf][1] * inv0);
        g_ctx[row1 + c0] = to_tf32(o[nf][2] * inv1);
        g_ctx[row1 + c1] = to_tf32(o[nf][3] * inv1);
    }
}

// ---------------------------------------------------------------------------
extern "C" void kernel_launch(void* const* d_in, const int* in_sizes, int n_in,
                              void* d_out, int out_size)
{
    const float* x  = (const float*)d_in[0];
    const float* Wq = (const float*)d_in[1];
    const float* Wk = (const float*)d_in[2];
    const float* Wv = (const float*)d_in[3];
    const float* Wo = (const float*)d_in[4];
    const float* bo = (const float*)d_in[5];
    float* out = (float*)d_out;

    cudaFuncSetAttribute(gemm_tc, cudaFuncAttributeMaxDynamicSharedMemorySize, GEMM_SMEM);
    cudaFuncSetAttribute(attn_tc, cudaFuncAttributeMaxDynamicSharedMemorySize, ATTN_SMEM);

    // one-time tf32 rounding + layout transforms
    prep_x<<<(MTOT * D_IN) / 256, 256>>>(x);
    dim3 tg(DMODEL / 32, D_IN / 32);
    prep_wt<<<tg, 256>>>(Wq, 0);
    prep_wt<<<tg, 256>>>(Wk, 1);
    prep_wt<<<tg, 256>>>(Wv, 2);
    prep_wt<<<tg, 256>>>(Wo, 3);

    // QKV projections -> g_q/g_k (frag layout), g_v (transposed)
    gemm_tc<<<dim3(8, 64, 3), 256, GEMM_SMEM>>>(nullptr, nullptr, 0);
    // causal flash attention
    attn_tc<<<dim3(32, 64), 128, ATTN_SMEM>>>();
    // output projection + bias
    gemm_tc<<<dim3(8, 64, 1), 256, GEMM_SMEM>>>(bo, out, 1);
}